// round 1
// baseline (speedup 1.0000x reference)
#include <cuda_runtime.h>

#define NPTS     8192
#define TPB      256
#define JCHUNK   1024
#define MIN_DISTF 0.1f
#define MIN_D2F   0.01f

// scratch accumulators: [0] = sum of squared errors (MSE numerator), [1] = penalty sum
__device__ double g_acc[2];

__device__ __forceinline__ float warp_reduce_sum(float v) {
#pragma unroll
    for (int o = 16; o > 0; o >>= 1)
        v += __shfl_xor_sync(0xffffffffu, v, o);
    return v;
}

__device__ __forceinline__ void block_reduce_atomic(float v, int slot) {
    __shared__ float sm[TPB / 32];
    int lane = threadIdx.x & 31;
    int w    = threadIdx.x >> 5;
    v = warp_reduce_sum(v);
    if (lane == 0) sm[w] = v;
    __syncthreads();
    if (w == 0) {
        float x = (lane < TPB / 32) ? sm[lane] : 0.f;
        x = warp_reduce_sum(x);
        if (lane == 0) atomicAdd(&g_acc[slot], (double)x);
    }
}

__global__ void k_zero() {
    if (threadIdx.x < 2) g_acc[threadIdx.x] = 0.0;
}

__global__ void k_mse(const float4* __restrict__ p, const float4* __restrict__ t) {
    int idx = blockIdx.x * TPB + threadIdx.x;
    float s = 0.f;
    const int n4 = (NPTS * 2) / 4;  // 4096 float4's
    for (int i = idx; i < n4; i += gridDim.x * TPB) {
        float4 a = p[i], b = t[i];
        float d0 = a.x - b.x, d1 = a.y - b.y, d2 = a.z - b.z, d3 = a.w - b.w;
        s = fmaf(d0, d0, s);
        s = fmaf(d1, d1, s);
        s = fmaf(d2, d2, s);
        s = fmaf(d3, d3, s);
    }
    block_reduce_atomic(s, 0);
}

// Pairwise proximity penalty over strict upper triangle (i < j).
// Grid: (NPTS/TPB, NPTS/JCHUNK). Block (bx,by): i in [bx*TPB, ...), j-chunk [by*JCHUNK, ...).
__global__ void k_pairs(const float2* __restrict__ pts) {
    const int ibase = blockIdx.x * TPB;
    const int jbase = blockIdx.y * JCHUNK;

    // whole chunk below-or-on diagonal -> no (i<j) pairs -> skip
    if (jbase + JCHUNK <= ibase) return;

    __shared__ float2 tile[JCHUNK];
    const int    i  = ibase + threadIdx.x;
    const float2 pi = pts[i];

    for (int k = threadIdx.x; k < JCHUNK; k += TPB)
        tile[k] = pts[jbase + k];
    __syncthreads();

    float acc = 0.f;
    if (jbase >= ibase + TPB) {
        // chunk entirely strictly above diagonal for every i in this block: no per-pair check
#pragma unroll 8
        for (int k = 0; k < JCHUNK; k++) {
            float dx = pi.x - tile[k].x;
            float dy = pi.y - tile[k].y;
            float d2 = fmaf(dx, dx, dy * dy);
            if (d2 < MIN_D2F) {
                float m = MIN_DISTF - sqrtf(d2);
                acc = fmaf(m, m, acc);
            }
        }
    } else {
        // straddles the diagonal: predicate on j > i
#pragma unroll 4
        for (int k = 0; k < JCHUNK; k++) {
            int   j  = jbase + k;
            float dx = pi.x - tile[k].x;
            float dy = pi.y - tile[k].y;
            float d2 = fmaf(dx, dx, dy * dy);
            if (d2 < MIN_D2F && j > i) {
                float m = MIN_DISTF - sqrtf(d2);
                acc = fmaf(m, m, acc);
            }
        }
    }
    block_reduce_atomic(acc, 1);
}

__global__ void k_final(float* __restrict__ out) {
    out[0] = (float)(g_acc[0] * (1.0 / (double)(NPTS * 2)) + g_acc[1]);
}

extern "C" void kernel_launch(void* const* d_in, const int* in_sizes, int n_in,
                              void* d_out, int out_size) {
    const float* pred = (const float*)d_in[0];
    const float* targ = (const float*)d_in[1];

    k_zero<<<1, 32>>>();
    k_mse<<<8, TPB>>>((const float4*)pred, (const float4*)targ);
    k_pairs<<<dim3(NPTS / TPB, NPTS / JCHUNK), TPB>>>((const float2*)pred);
    k_final<<<1, 1>>>((float*)d_out);
}